// round 7
// baseline (speedup 1.0000x reference)
#include <cuda_runtime.h>

// ---------------- problem constants ----------------
#define BV    4      // batch
#define NCAM  6      // cameras
#define DDEP  41     // depth bins
#define FHH   8      // feature H
#define FWW   22     // feature W
#define CC    128    // channels
#define NXX   200
#define NYY   200
#define NPTS  (BV*NCAM*DDEP*FHH*FWW)   // 173184
#define NVOX  (NXX*NYY*BV)             // 160000

// ---------------- static scratch (no allocations allowed) ----------------
__device__ int   g_head[NVOX];
__device__ int   g_next[NPTS];
// per-cam: Pinv[9], post_trans[3], combine[9], trans[3]
__device__ float g_cam[BV*NCAM][24];

// strict separately-rounded dot-3: ((a0*b0 + a1*b1) + a2*b2), no FMA contraction
__device__ __forceinline__ float dot3_strict(float a0, float a1, float a2,
                                             float b0, float b1, float b2) {
    float p0 = __fmul_rn(a0, b0);
    float p1 = __fmul_rn(a1, b1);
    float p2 = __fmul_rn(a2, b2);
    return __fadd_rn(__fadd_rn(p0, p1), p2);
}

// ---------------- 3x3 inverse emulating jnp.linalg.inv (GPU path) ----------------
// (Identical to R6 — proven output-equivalent to R5's variant on these inputs.)
__device__ void inv3_lu(const float* __restrict__ A, float* __restrict__ X) {
    float a[3][3];
    #pragma unroll
    for (int r = 0; r < 3; r++)
        #pragma unroll
        for (int c = 0; c < 3; c++)
            a[r][c] = A[r*3+c];
    int piv[3] = {0, 1, 2};

    // k = 0: pivot = first occurrence of max |a[i][0]|
    {
        int p = 0;
        float m = fabsf(a[0][0]);
        if (fabsf(a[1][0]) > m) { m = fabsf(a[1][0]); p = 1; }
        if (fabsf(a[2][0]) > m) { p = 2; }
        if (p != 0) {
            #pragma unroll
            for (int c = 0; c < 3; c++) { float t = a[0][c]; a[0][c] = a[p][c]; a[p][c] = t; }
            int t = piv[0]; piv[0] = piv[p]; piv[p] = t;
        }
        float rcp = 1.0f / a[0][0];          // correctly-rounded reciprocal
        float l10 = __fmul_rn(a[1][0], rcp);
        float l20 = __fmul_rn(a[2][0], rcp);
        a[1][1] = fmaf(-l10, a[0][1], a[1][1]);
        a[1][2] = fmaf(-l10, a[0][2], a[1][2]);
        a[2][1] = fmaf(-l20, a[0][1], a[2][1]);
        a[2][2] = fmaf(-l20, a[0][2], a[2][2]);
        a[1][0] = l10; a[2][0] = l20;
    }
    // k = 1
    {
        if (fabsf(a[2][1]) > fabsf(a[1][1])) {
            #pragma unroll
            for (int c = 0; c < 3; c++) { float t = a[1][c]; a[1][c] = a[2][c]; a[2][c] = t; }
            int t = piv[1]; piv[1] = piv[2]; piv[2] = t;
        }
        float rcp = 1.0f / a[1][1];
        float l21 = __fmul_rn(a[2][1], rcp);
        a[2][2] = fmaf(-l21, a[1][2], a[2][2]);
        a[2][1] = l21;
    }

    // hoisted diagonal reciprocals for the upper solve
    float r00 = 1.0f / a[0][0];
    float r11 = 1.0f / a[1][1];
    float r22 = 1.0f / a[2][2];

    // solve for each unit column of the identity
    #pragma unroll
    for (int c = 0; c < 3; c++) {
        float b0 = (piv[0] == c) ? 1.0f : 0.0f;
        float b1 = (piv[1] == c) ? 1.0f : 0.0f;
        float b2 = (piv[2] == c) ? 1.0f : 0.0f;
        // forward (unit lower)
        float y0 = b0;
        float y1 = fmaf(-a[1][0], y0, b1);
        float y2 = fmaf(-a[2][1], y1, fmaf(-a[2][0], y0, b2));
        // backward (upper), reciprocal-multiply; u02 applied before u01
        float x2 = __fmul_rn(y2, r22);
        float x1 = __fmul_rn(fmaf(-a[1][2], x2, y1), r11);
        float x0 = __fmul_rn(fmaf(-a[0][1], x1, fmaf(-a[0][2], x2, y0)), r00);
        X[0*3+c] = x0; X[1*3+c] = x1; X[2*3+c] = x2;
    }
}

// ---------------- K0: per-camera matrices (24 cams) ----------------
__global__ void k_setup(const float* __restrict__ rots,
                        const float* __restrict__ trans,
                        const float* __restrict__ intrins,
                        const float* __restrict__ post_rots,
                        const float* __restrict__ post_trans) {
    int i = threadIdx.x;
    if (i >= BV*NCAM) return;
    float P[9], Ki[9];
    inv3_lu(post_rots + i*9, P);
    inv3_lu(intrins  + i*9, Ki);
    const float* R  = rots + i*9;
    float* cm = g_cam[i];
    #pragma unroll
    for (int r = 0; r < 9; r++) cm[r] = P[r];
    #pragma unroll
    for (int r = 0; r < 3; r++) cm[9+r] = post_trans[i*3+r];
    // combine = rots @ inv(intrins): strict mul/add ascending (R6-identical)
    #pragma unroll
    for (int r = 0; r < 3; r++)
        #pragma unroll
        for (int c = 0; c < 3; c++)
            cm[12 + r*3 + c] = dot3_strict(R[r*3+0], R[r*3+1], R[r*3+2],
                                           Ki[0*3+c], Ki[1*3+c], Ki[2*3+c]);
    #pragma unroll
    for (int r = 0; r < 3; r++) cm[21+r] = trans[i*3+r];
}

// ---------------- K1: init voxel list heads ----------------
__global__ void k_init_head() {
    int i = blockIdx.x * blockDim.x + threadIdx.x;
    if (i < NVOX) g_head[i] = -1;
}

// ---------------- K2: per-point geometry + linked-list insert ----------------
__global__ void k_geom() {
    int p = blockIdx.x * blockDim.x + threadIdx.x;
    if (p >= NPTS) return;

    int w = p % FWW;
    int t = p / FWW;
    int h = t % FHH;  t /= FHH;
    int d = t % DDEP;
    int cam = t / DDEP;            // b*NCAM + n
    int b   = cam / NCAM;

    // linspace WITHOUT endpoint fixup (R7 change): out = start + iota*delta,
    // delta = fl((stop-start)/div). Last element = fl(div*delta), NOT forced
    // to stop. (R6 forced the endpoint; testing the unforced lowering.)
    const float stepx = 351.0f / 21.0f;   // compile-time fp32 constant
    const float stepy = 127.0f / 7.0f;
    float fx = __fmul_rn((float)w, stepx);
    float fy = __fmul_rn((float)h, stepy);
    float fd = 4.0f + (float)d;

    const float* cm = g_cam[cam];

    // pts = frustum - post_trans   (eager elementwise sub)
    float s0 = __fadd_rn(fx, -cm[9]);
    float s1 = __fadd_rn(fy, -cm[10]);
    float s2 = __fadd_rn(fd, -cm[11]);

    // pts = inv(post_rots) @ pts  — strict mul/add ascending
    float p2x = dot3_strict(cm[0], cm[1], cm[2], s0, s1, s2);
    float p2y = dot3_strict(cm[3], cm[4], cm[5], s0, s1, s2);
    float p2z = dot3_strict(cm[6], cm[7], cm[8], s0, s1, s2);

    // un-normalize: (u*z, v*z, z)
    float p3x = __fmul_rn(p2x, p2z);
    float p3y = __fmul_rn(p2y, p2z);
    float p3z = p2z;

    // ego = combine @ p3 (strict) + trans (separate add)
    float ex = __fadd_rn(dot3_strict(cm[12], cm[13], cm[14], p3x, p3y, p3z), cm[21]);
    float ey = __fadd_rn(dot3_strict(cm[15], cm[16], cm[17], p3x, p3y, p3z), cm[22]);
    float ez = __fadd_rn(dot3_strict(cm[18], cm[19], cm[20], p3x, p3y, p3z), cm[23]);

    // bin: (pts - (-50,-50,-10)) / (0.5,0.5,20), trunc toward zero
    float vx = __fadd_rn(ex, 50.0f) / 0.5f;    // exact (po2 divisor)
    float vy = __fadd_rn(ey, 50.0f) / 0.5f;
    float vz = __fdiv_rn(__fadd_rn(ez, 10.0f), 20.0f);
    int gx = (int)vx;
    int gy = (int)vy;
    int gz = (int)vz;

    if (gx >= 0 && gx < NXX && gy >= 0 && gy < NYY && gz == 0) {
        int vox = (gx * NYY + gy) * BV + b;
        int old = atomicExch(&g_head[vox], p);
        g_next[p] = old;   // safe: traversal happens in a later kernel
    }
}

// ---------------- K3: gather per voxel, write transposed output ----------------
// block: (32 y, 16 tc) ; thread accumulates 8 channels c = tc*8 + j
// grid:  (ceil(NY/32), NX, B)
__global__ __launch_bounds__(512) void k_gather(const float* __restrict__ feats,
                                                float* __restrict__ out) {
    int ty = threadIdx.x;          // y within tile
    int tc = threadIdx.y;          // channel group
    int y  = blockIdx.x * 32 + ty;
    int x  = blockIdx.y;
    int b  = blockIdx.z;
    if (y >= NYY) return;

    float acc[8];
    #pragma unroll
    for (int j = 0; j < 8; j++) acc[j] = 0.0f;

    int vox = (x * NYY + y) * BV + b;
    int p = g_head[vox];
    while (p >= 0) {
        const float4* row = reinterpret_cast<const float4*>(feats + (size_t)p * CC + tc * 8);
        float4 r0 = row[0];
        float4 r1 = row[1];
        acc[0] += r0.x; acc[1] += r0.y; acc[2] += r0.z; acc[3] += r0.w;
        acc[4] += r1.x; acc[5] += r1.y; acc[6] += r1.z; acc[7] += r1.w;
        p = g_next[p];
    }

    // out[b][c][x][y], c = tc*8 + j ; coalesced over y within each warp
    size_t base = ((size_t)(b * CC + tc * 8) * NXX + x) * NYY + y;
    #pragma unroll
    for (int j = 0; j < 8; j++)
        out[base + (size_t)j * NXX * NYY] = acc[j];
}

// ---------------- launch ----------------
extern "C" void kernel_launch(void* const* d_in, const int* in_sizes, int n_in,
                              void* d_out, int out_size) {
    const float* cam_feats  = (const float*)d_in[0];
    const float* rots       = (const float*)d_in[1];
    const float* trans      = (const float*)d_in[2];
    const float* intrins    = (const float*)d_in[3];
    const float* post_rots  = (const float*)d_in[4];
    const float* post_trans = (const float*)d_in[5];
    float* out = (float*)d_out;

    k_setup<<<1, 32>>>(rots, trans, intrins, post_rots, post_trans);
    k_init_head<<<(NVOX + 255) / 256, 256>>>();
    k_geom<<<(NPTS + 255) / 256, 256>>>();

    dim3 gblock(32, 16);
    dim3 ggrid((NYY + 31) / 32, NXX, BV);
    k_gather<<<ggrid, gblock>>>(cam_feats, out);
}

// round 8
// speedup vs baseline: 1.1526x; 1.1526x over previous
#include <cuda_runtime.h>

// ---------------- problem constants ----------------
#define BV    4      // batch
#define NCAM  6      // cameras
#define DDEP  41     // depth bins
#define FHH   8      // feature H
#define FWW   22     // feature W
#define CC    128    // channels
#define NXX   200
#define NYY   200
#define NPTS  (BV*NCAM*DDEP*FHH*FWW)   // 173184
#define NVOX  (NXX*NYY*BV)             // 160000

#define SCAN_THREADS 256
#define SCAN_ELEMS   4
#define SCAN_BLOCK   (SCAN_THREADS*SCAN_ELEMS)              // 1024
#define NSCAN_BLOCKS ((NVOX + SCAN_BLOCK - 1) / SCAN_BLOCK) // 157

// ---------------- static scratch (no allocations allowed) ----------------
__device__ int   g_count[NVOX];    // points per voxel
__device__ int   g_off[NVOX];      // exclusive offset within scan-block
__device__ int   g_bsum[256];      // per-scan-block totals -> exclusive bases
__device__ int   g_pvox[NPTS];     // voxel id per point (-1 dropped)
__device__ int   g_prank[NPTS];    // rank of point within its voxel
__device__ int   g_idx[NPTS];      // CSR point indices
// per-cam: Pinv[9], post_trans[3], combine[9], trans[3]
__device__ float g_cam[BV*NCAM][24];

// strict separately-rounded dot-3 (FROZEN — matches reference bit-exactly)
__device__ __forceinline__ float dot3_strict(float a0, float a1, float a2,
                                             float b0, float b1, float b2) {
    float p0 = __fmul_rn(a0, b0);
    float p1 = __fmul_rn(a1, b1);
    float p2 = __fmul_rn(a2, b2);
    return __fadd_rn(__fadd_rn(p0, p1), p2);
}

// ---------------- 3x3 inverse (FROZEN — R6/R7 verified) ----------------
__device__ void inv3_lu(const float* __restrict__ A, float* __restrict__ X) {
    float a[3][3];
    #pragma unroll
    for (int r = 0; r < 3; r++)
        #pragma unroll
        for (int c = 0; c < 3; c++)
            a[r][c] = A[r*3+c];
    int piv[3] = {0, 1, 2};
    {
        int p = 0;
        float m = fabsf(a[0][0]);
        if (fabsf(a[1][0]) > m) { m = fabsf(a[1][0]); p = 1; }
        if (fabsf(a[2][0]) > m) { p = 2; }
        if (p != 0) {
            #pragma unroll
            for (int c = 0; c < 3; c++) { float t = a[0][c]; a[0][c] = a[p][c]; a[p][c] = t; }
            int t = piv[0]; piv[0] = piv[p]; piv[p] = t;
        }
        float rcp = 1.0f / a[0][0];
        float l10 = __fmul_rn(a[1][0], rcp);
        float l20 = __fmul_rn(a[2][0], rcp);
        a[1][1] = fmaf(-l10, a[0][1], a[1][1]);
        a[1][2] = fmaf(-l10, a[0][2], a[1][2]);
        a[2][1] = fmaf(-l20, a[0][1], a[2][1]);
        a[2][2] = fmaf(-l20, a[0][2], a[2][2]);
        a[1][0] = l10; a[2][0] = l20;
    }
    {
        if (fabsf(a[2][1]) > fabsf(a[1][1])) {
            #pragma unroll
            for (int c = 0; c < 3; c++) { float t = a[1][c]; a[1][c] = a[2][c]; a[2][c] = t; }
            int t = piv[1]; piv[1] = piv[2]; piv[2] = t;
        }
        float rcp = 1.0f / a[1][1];
        float l21 = __fmul_rn(a[2][1], rcp);
        a[2][2] = fmaf(-l21, a[1][2], a[2][2]);
        a[2][1] = l21;
    }
    float r00 = 1.0f / a[0][0];
    float r11 = 1.0f / a[1][1];
    float r22 = 1.0f / a[2][2];
    #pragma unroll
    for (int c = 0; c < 3; c++) {
        float b0 = (piv[0] == c) ? 1.0f : 0.0f;
        float b1 = (piv[1] == c) ? 1.0f : 0.0f;
        float b2 = (piv[2] == c) ? 1.0f : 0.0f;
        float y0 = b0;
        float y1 = fmaf(-a[1][0], y0, b1);
        float y2 = fmaf(-a[2][1], y1, fmaf(-a[2][0], y0, b2));
        float x2 = __fmul_rn(y2, r22);
        float x1 = __fmul_rn(fmaf(-a[1][2], x2, y1), r11);
        float x0 = __fmul_rn(fmaf(-a[0][1], x1, fmaf(-a[0][2], x2, y0)), r00);
        X[0*3+c] = x0; X[1*3+c] = x1; X[2*3+c] = x2;
    }
}

// ---------------- K0: per-camera matrices (FROZEN math) ----------------
__global__ void k_setup(const float* __restrict__ rots,
                        const float* __restrict__ trans,
                        const float* __restrict__ intrins,
                        const float* __restrict__ post_rots,
                        const float* __restrict__ post_trans) {
    int i = threadIdx.x;
    if (i >= BV*NCAM) return;
    float P[9], Ki[9];
    inv3_lu(post_rots + i*9, P);
    inv3_lu(intrins  + i*9, Ki);
    const float* R  = rots + i*9;
    float* cm = g_cam[i];
    #pragma unroll
    for (int r = 0; r < 9; r++) cm[r] = P[r];
    #pragma unroll
    for (int r = 0; r < 3; r++) cm[9+r] = post_trans[i*3+r];
    #pragma unroll
    for (int r = 0; r < 3; r++)
        #pragma unroll
        for (int c = 0; c < 3; c++)
            cm[12 + r*3 + c] = dot3_strict(R[r*3+0], R[r*3+1], R[r*3+2],
                                           Ki[0*3+c], Ki[1*3+c], Ki[2*3+c]);
    #pragma unroll
    for (int r = 0; r < 3; r++) cm[21+r] = trans[i*3+r];
}

// ---------------- K1: zero per-voxel counters ----------------
__global__ void k_zero() {
    int i = blockIdx.x * blockDim.x + threadIdx.x;
    if (i < NVOX) g_count[i] = 0;
}

// ---------------- K2: geometry (FROZEN) + count/rank ----------------
__global__ void k_geom() {
    int p = blockIdx.x * blockDim.x + threadIdx.x;
    if (p >= NPTS) return;

    int w = p % FWW;
    int t = p / FWW;
    int h = t % FHH;  t /= FHH;
    int d = t % DDEP;
    int cam = t / DDEP;            // b*NCAM + n
    int b   = cam / NCAM;

    // linspace WITHOUT endpoint fixup (verified bit-exact in R7)
    const float stepx = 351.0f / 21.0f;
    const float stepy = 127.0f / 7.0f;
    float fx = __fmul_rn((float)w, stepx);
    float fy = __fmul_rn((float)h, stepy);
    float fd = 4.0f + (float)d;

    const float* cm = g_cam[cam];

    float s0 = __fadd_rn(fx, -cm[9]);
    float s1 = __fadd_rn(fy, -cm[10]);
    float s2 = __fadd_rn(fd, -cm[11]);

    float p2x = dot3_strict(cm[0], cm[1], cm[2], s0, s1, s2);
    float p2y = dot3_strict(cm[3], cm[4], cm[5], s0, s1, s2);
    float p2z = dot3_strict(cm[6], cm[7], cm[8], s0, s1, s2);

    float p3x = __fmul_rn(p2x, p2z);
    float p3y = __fmul_rn(p2y, p2z);
    float p3z = p2z;

    float ex = __fadd_rn(dot3_strict(cm[12], cm[13], cm[14], p3x, p3y, p3z), cm[21]);
    float ey = __fadd_rn(dot3_strict(cm[15], cm[16], cm[17], p3x, p3y, p3z), cm[22]);
    float ez = __fadd_rn(dot3_strict(cm[18], cm[19], cm[20], p3x, p3y, p3z), cm[23]);

    float vx = __fadd_rn(ex, 50.0f) / 0.5f;
    float vy = __fadd_rn(ey, 50.0f) / 0.5f;
    float vz = __fdiv_rn(__fadd_rn(ez, 10.0f), 20.0f);
    int gx = (int)vx;
    int gy = (int)vy;
    int gz = (int)vz;

    int vox = -1, rank = 0;
    if (gx >= 0 && gx < NXX && gy >= 0 && gy < NYY && gz == 0) {
        vox = (gx * NYY + gy) * BV + b;
        rank = atomicAdd(&g_count[vox], 1);
    }
    g_pvox[p]  = vox;
    g_prank[p] = rank;
}

// ---------------- K3: scan level 1 (per 1024-voxel block) ----------------
__global__ __launch_bounds__(SCAN_THREADS) void k_scan1() {
    __shared__ int s[SCAN_THREADS];
    int bb = blockIdx.x, t = threadIdx.x;
    int base = bb * SCAN_BLOCK + t * SCAN_ELEMS;
    int v[SCAN_ELEMS];
    int sum = 0;
    #pragma unroll
    for (int j = 0; j < SCAN_ELEMS; j++) {
        v[j] = (base + j < NVOX) ? g_count[base + j] : 0;
        sum += v[j];
    }
    s[t] = sum;
    __syncthreads();
    // Hillis-Steele inclusive scan over 256 thread sums
    #pragma unroll
    for (int off = 1; off < SCAN_THREADS; off <<= 1) {
        int x = (t >= off) ? s[t - off] : 0;
        __syncthreads();
        s[t] += x;
        __syncthreads();
    }
    int excl = s[t] - sum;
    if (t == SCAN_THREADS - 1) g_bsum[bb] = s[t];
    int run = excl;
    #pragma unroll
    for (int j = 0; j < SCAN_ELEMS; j++) {
        if (base + j < NVOX) { g_off[base + j] = run; run += v[j]; }
    }
}

// ---------------- K4: scan level 2 (block bases, exclusive) ----------------
__global__ __launch_bounds__(256) void k_scan2() {
    __shared__ int s[256];
    int t = threadIdx.x;
    int v = (t < NSCAN_BLOCKS) ? g_bsum[t] : 0;
    s[t] = v;
    __syncthreads();
    #pragma unroll
    for (int off = 1; off < 256; off <<= 1) {
        int x = (t >= off) ? s[t - off] : 0;
        __syncthreads();
        s[t] += x;
        __syncthreads();
    }
    g_bsum[t] = s[t] - v;   // exclusive base
}

// ---------------- K5: fill CSR index array ----------------
__global__ void k_fill() {
    int p = blockIdx.x * blockDim.x + threadIdx.x;
    if (p >= NPTS) return;
    int vox = g_pvox[p];
    if (vox >= 0) {
        int o = g_off[vox] + g_bsum[vox >> 10];
        g_idx[o + g_prank[p]] = p;
    }
}

// ---------------- K6: CSR gather, write transposed output ----------------
// block: (32 y, 16 tc) ; thread accumulates 8 channels c = tc*8 + j
__global__ __launch_bounds__(512) void k_gather(const float* __restrict__ feats,
                                                float* __restrict__ out) {
    int ty = threadIdx.x;          // y within tile
    int tc = threadIdx.y;          // channel group
    int y  = blockIdx.x * 32 + ty;
    int x  = blockIdx.y;
    int b  = blockIdx.z;
    if (y >= NYY) return;

    float acc[8];
    #pragma unroll
    for (int j = 0; j < 8; j++) acc[j] = 0.0f;

    int vox = (x * NYY + y) * BV + b;
    int cnt = g_count[vox];
    int off = g_off[vox] + g_bsum[vox >> 10];
    const int* idx = g_idx + off;

    int j = 0;
    for (; j + 1 < cnt; j += 2) {
        int p0 = idx[j];
        int p1 = idx[j + 1];
        const float4* r0p = reinterpret_cast<const float4*>(feats + (size_t)p0 * CC + tc * 8);
        const float4* r1p = reinterpret_cast<const float4*>(feats + (size_t)p1 * CC + tc * 8);
        float4 a0 = r0p[0], a1 = r0p[1];
        float4 b0 = r1p[0], b1 = r1p[1];
        acc[0] += a0.x + b0.x; acc[1] += a0.y + b0.y;
        acc[2] += a0.z + b0.z; acc[3] += a0.w + b0.w;
        acc[4] += a1.x + b1.x; acc[5] += a1.y + b1.y;
        acc[6] += a1.z + b1.z; acc[7] += a1.w + b1.w;
    }
    if (j < cnt) {
        int p0 = idx[j];
        const float4* r0p = reinterpret_cast<const float4*>(feats + (size_t)p0 * CC + tc * 8);
        float4 a0 = r0p[0], a1 = r0p[1];
        acc[0] += a0.x; acc[1] += a0.y; acc[2] += a0.z; acc[3] += a0.w;
        acc[4] += a1.x; acc[5] += a1.y; acc[6] += a1.z; acc[7] += a1.w;
    }

    // out[b][c][x][y], c = tc*8 + j ; coalesced over y within each warp
    size_t base = ((size_t)(b * CC + tc * 8) * NXX + x) * NYY + y;
    #pragma unroll
    for (int j2 = 0; j2 < 8; j2++)
        out[base + (size_t)j2 * NXX * NYY] = acc[j2];
}

// ---------------- launch ----------------
extern "C" void kernel_launch(void* const* d_in, const int* in_sizes, int n_in,
                              void* d_out, int out_size) {
    const float* cam_feats  = (const float*)d_in[0];
    const float* rots       = (const float*)d_in[1];
    const float* trans      = (const float*)d_in[2];
    const float* intrins    = (const float*)d_in[3];
    const float* post_rots  = (const float*)d_in[4];
    const float* post_trans = (const float*)d_in[5];
    float* out = (float*)d_out;

    k_setup<<<1, 32>>>(rots, trans, intrins, post_rots, post_trans);
    k_zero<<<(NVOX + 255) / 256, 256>>>();
    k_geom<<<(NPTS + 255) / 256, 256>>>();
    k_scan1<<<NSCAN_BLOCKS, SCAN_THREADS>>>();
    k_scan2<<<1, 256>>>();
    k_fill<<<(NPTS + 255) / 256, 256>>>();

    dim3 gblock(32, 16);
    dim3 ggrid((NYY + 31) / 32, NXX, BV);
    k_gather<<<ggrid, gblock>>>(cam_feats, out);
}

// round 9
// speedup vs baseline: 1.2450x; 1.0801x over previous
#include <cuda_runtime.h>

// ---------------- problem constants ----------------
#define BV    4      // batch
#define NCAM  6      // cameras
#define DDEP  41     // depth bins
#define FHH   8      // feature H
#define FWW   22     // feature W
#define CC    128    // channels
#define NXX   200
#define NYY   200
#define NPTS  (BV*NCAM*DDEP*FHH*FWW)   // 173184
#define NVOX  (NXX*NYY*BV)             // 160000

#define SCAN_BLOCK   1024
#define NSCAN_BLOCKS ((NVOX + SCAN_BLOCK - 1) / SCAN_BLOCK) // 157

// ---------------- static scratch (no allocations allowed) ----------------
__device__ __align__(16) int g_count[NVOX];  // points per voxel
__device__ __align__(16) int g_off[NVOX];    // exclusive offset within scan-block
__device__ int   g_bsum[256];                // per-scan-block totals -> exclusive bases
__device__ int   g_pvox[NPTS];               // voxel id per point (-1 dropped)
__device__ int   g_prank[NPTS];              // rank of point within its voxel
__device__ int   g_idx[NPTS];                // CSR point indices
// per-cam: Pinv[9], post_trans[3], combine[9], trans[3]
__device__ float g_cam[BV*NCAM][24];

// strict separately-rounded dot-3 (FROZEN — matches reference bit-exactly)
__device__ __forceinline__ float dot3_strict(float a0, float a1, float a2,
                                             float b0, float b1, float b2) {
    float p0 = __fmul_rn(a0, b0);
    float p1 = __fmul_rn(a1, b1);
    float p2 = __fmul_rn(a2, b2);
    return __fadd_rn(__fadd_rn(p0, p1), p2);
}

// ---------------- 3x3 inverse (FROZEN — R6/R7 verified) ----------------
__device__ void inv3_lu(const float* __restrict__ A, float* __restrict__ X) {
    float a[3][3];
    #pragma unroll
    for (int r = 0; r < 3; r++)
        #pragma unroll
        for (int c = 0; c < 3; c++)
            a[r][c] = A[r*3+c];
    int piv[3] = {0, 1, 2};
    {
        int p = 0;
        float m = fabsf(a[0][0]);
        if (fabsf(a[1][0]) > m) { m = fabsf(a[1][0]); p = 1; }
        if (fabsf(a[2][0]) > m) { p = 2; }
        if (p != 0) {
            #pragma unroll
            for (int c = 0; c < 3; c++) { float t = a[0][c]; a[0][c] = a[p][c]; a[p][c] = t; }
            int t = piv[0]; piv[0] = piv[p]; piv[p] = t;
        }
        float rcp = 1.0f / a[0][0];
        float l10 = __fmul_rn(a[1][0], rcp);
        float l20 = __fmul_rn(a[2][0], rcp);
        a[1][1] = fmaf(-l10, a[0][1], a[1][1]);
        a[1][2] = fmaf(-l10, a[0][2], a[1][2]);
        a[2][1] = fmaf(-l20, a[0][1], a[2][1]);
        a[2][2] = fmaf(-l20, a[0][2], a[2][2]);
        a[1][0] = l10; a[2][0] = l20;
    }
    {
        if (fabsf(a[2][1]) > fabsf(a[1][1])) {
            #pragma unroll
            for (int c = 0; c < 3; c++) { float t = a[1][c]; a[1][c] = a[2][c]; a[2][c] = t; }
            int t = piv[1]; piv[1] = piv[2]; piv[2] = t;
        }
        float rcp = 1.0f / a[1][1];
        float l21 = __fmul_rn(a[2][1], rcp);
        a[2][2] = fmaf(-l21, a[1][2], a[2][2]);
        a[2][1] = l21;
    }
    float r00 = 1.0f / a[0][0];
    float r11 = 1.0f / a[1][1];
    float r22 = 1.0f / a[2][2];
    #pragma unroll
    for (int c = 0; c < 3; c++) {
        float b0 = (piv[0] == c) ? 1.0f : 0.0f;
        float b1 = (piv[1] == c) ? 1.0f : 0.0f;
        float b2 = (piv[2] == c) ? 1.0f : 0.0f;
        float y0 = b0;
        float y1 = fmaf(-a[1][0], y0, b1);
        float y2 = fmaf(-a[2][1], y1, fmaf(-a[2][0], y0, b2));
        float x2 = __fmul_rn(y2, r22);
        float x1 = __fmul_rn(fmaf(-a[1][2], x2, y1), r11);
        float x0 = __fmul_rn(fmaf(-a[0][1], x1, fmaf(-a[0][2], x2, y0)), r00);
        X[0*3+c] = x0; X[1*3+c] = x1; X[2*3+c] = x2;
    }
}

// ---------------- K0: zero counters + camera matrices (fused) ----------------
__global__ void k_init(const float* __restrict__ rots,
                       const float* __restrict__ trans,
                       const float* __restrict__ intrins,
                       const float* __restrict__ post_rots,
                       const float* __restrict__ post_trans) {
    int i = blockIdx.x * blockDim.x + threadIdx.x;
    if (i < NVOX) g_count[i] = 0;
    if (blockIdx.x == 0 && threadIdx.x < BV*NCAM) {
        int c = threadIdx.x;
        float P[9], Ki[9];
        inv3_lu(post_rots + c*9, P);
        inv3_lu(intrins  + c*9, Ki);
        const float* R  = rots + c*9;
        float* cm = g_cam[c];
        #pragma unroll
        for (int r = 0; r < 9; r++) cm[r] = P[r];
        #pragma unroll
        for (int r = 0; r < 3; r++) cm[9+r] = post_trans[c*3+r];
        #pragma unroll
        for (int r = 0; r < 3; r++)
            #pragma unroll
            for (int cc2 = 0; cc2 < 3; cc2++)
                cm[12 + r*3 + cc2] = dot3_strict(R[r*3+0], R[r*3+1], R[r*3+2],
                                                 Ki[0*3+cc2], Ki[1*3+cc2], Ki[2*3+cc2]);
        #pragma unroll
        for (int r = 0; r < 3; r++) cm[21+r] = trans[c*3+r];
    }
}

// ---------------- K1: geometry (FROZEN) + count/rank ----------------
__global__ void k_geom() {
    int p = blockIdx.x * blockDim.x + threadIdx.x;
    if (p >= NPTS) return;

    int w = p % FWW;
    int t = p / FWW;
    int h = t % FHH;  t /= FHH;
    int d = t % DDEP;
    int cam = t / DDEP;            // b*NCAM + n
    int b   = cam / NCAM;

    // linspace WITHOUT endpoint fixup (verified bit-exact in R7)
    const float stepx = 351.0f / 21.0f;
    const float stepy = 127.0f / 7.0f;
    float fx = __fmul_rn((float)w, stepx);
    float fy = __fmul_rn((float)h, stepy);
    float fd = 4.0f + (float)d;

    const float* cm = g_cam[cam];

    float s0 = __fadd_rn(fx, -cm[9]);
    float s1 = __fadd_rn(fy, -cm[10]);
    float s2 = __fadd_rn(fd, -cm[11]);

    float p2x = dot3_strict(cm[0], cm[1], cm[2], s0, s1, s2);
    float p2y = dot3_strict(cm[3], cm[4], cm[5], s0, s1, s2);
    float p2z = dot3_strict(cm[6], cm[7], cm[8], s0, s1, s2);

    float p3x = __fmul_rn(p2x, p2z);
    float p3y = __fmul_rn(p2y, p2z);
    float p3z = p2z;

    float ex = __fadd_rn(dot3_strict(cm[12], cm[13], cm[14], p3x, p3y, p3z), cm[21]);
    float ey = __fadd_rn(dot3_strict(cm[15], cm[16], cm[17], p3x, p3y, p3z), cm[22]);
    float ez = __fadd_rn(dot3_strict(cm[18], cm[19], cm[20], p3x, p3y, p3z), cm[23]);

    float vx = __fadd_rn(ex, 50.0f) / 0.5f;
    float vy = __fadd_rn(ey, 50.0f) / 0.5f;
    float vz = __fdiv_rn(__fadd_rn(ez, 10.0f), 20.0f);
    int gx = (int)vx;
    int gy = (int)vy;
    int gz = (int)vz;

    int vox = -1, rank = 0;
    if (gx >= 0 && gx < NXX && gy >= 0 && gy < NYY && gz == 0) {
        vox = (gx * NYY + gy) * BV + b;
        rank = atomicAdd(&g_count[vox], 1);
    }
    g_pvox[p]  = vox;
    g_prank[p] = rank;
}

// ---------------- K2: scan level 1 (per 1024-voxel block, shfl-based) ----------------
__global__ __launch_bounds__(256) void k_scan1() {
    __shared__ int wsum[8];
    int bb = blockIdx.x, t = threadIdx.x;
    int lane = t & 31, wid = t >> 5;
    int base = bb * SCAN_BLOCK + t * 4;

    int v0 = 0, v1 = 0, v2 = 0, v3 = 0;
    if (base + 3 < NVOX) {
        int4 q = *reinterpret_cast<const int4*>(&g_count[base]);
        v0 = q.x; v1 = q.y; v2 = q.z; v3 = q.w;
    } else {
        if (base     < NVOX) v0 = g_count[base];
        if (base + 1 < NVOX) v1 = g_count[base + 1];
        if (base + 2 < NVOX) v2 = g_count[base + 2];
        if (base + 3 < NVOX) v3 = g_count[base + 3];
    }
    int s = v0 + v1 + v2 + v3;

    // warp inclusive scan of thread sums
    int incl = s;
    #pragma unroll
    for (int o = 1; o < 32; o <<= 1) {
        int x = __shfl_up_sync(0xffffffffu, incl, o);
        if (lane >= o) incl += x;
    }
    if (lane == 31) wsum[wid] = incl;
    __syncthreads();
    if (t < 8) {
        int w = wsum[t];
        int iw = w;
        #pragma unroll
        for (int o = 1; o < 8; o <<= 1) {
            int x = __shfl_up_sync(0xffu, iw, o);
            if (t >= o) iw += x;
        }
        wsum[t] = iw - w;     // exclusive warp base
    }
    __syncthreads();

    int excl = incl - s + wsum[wid];
    int run = excl;
    if (base     < NVOX) { g_off[base]     = run; run += v0; }
    if (base + 1 < NVOX) { g_off[base + 1] = run; run += v1; }
    if (base + 2 < NVOX) { g_off[base + 2] = run; run += v2; }
    if (base + 3 < NVOX) { g_off[base + 3] = run; }
    if (t == 255) g_bsum[bb] = excl + s;   // block total
}

// ---------------- K3: scan level 2 (block bases, exclusive) ----------------
__global__ __launch_bounds__(256) void k_scan2() {
    __shared__ int sh[256];
    int t = threadIdx.x;
    int v = (t < NSCAN_BLOCKS) ? g_bsum[t] : 0;
    sh[t] = v;
    __syncthreads();
    #pragma unroll
    for (int off = 1; off < 256; off <<= 1) {
        int x = (t >= off) ? sh[t - off] : 0;
        __syncthreads();
        sh[t] += x;
        __syncthreads();
    }
    g_bsum[t] = sh[t] - v;   // exclusive base
}

// ---------------- K4: fill CSR index array ----------------
__global__ void k_fill() {
    int p = blockIdx.x * blockDim.x + threadIdx.x;
    if (p >= NPTS) return;
    int vox = g_pvox[p];
    if (vox >= 0) {
        int o = g_off[vox] + g_bsum[vox >> 10];
        g_idx[o + g_prank[p]] = p;
    }
}

// ---------------- K5: warp-per-voxel CSR gather, smem transpose, coalesced IO ----
// block: 512 threads (16 warps). grid (7 ytiles, NX, B).
// Phase 1: each warp grabs y-voxels from a shared queue; 32 lanes read each
//          point's 512B feature row coalesced (lane*float4); acc 4 ch/lane.
// Phase 2: smem tile [32y][129c-padded] -> out writes contiguous along y.
__global__ __launch_bounds__(512) void k_gather(const float* __restrict__ feats,
                                                float* __restrict__ out) {
    __shared__ float tile[32][129];
    __shared__ int s_next;
    int tid  = threadIdx.x;
    int lane = tid & 31;
    int ytile = blockIdx.x, x = blockIdx.y, b = blockIdx.z;
    int ybase = ytile * 32;

    if (tid == 0) s_next = 0;
    __syncthreads();

    while (true) {
        int v;
        if (lane == 0) v = atomicAdd(&s_next, 1);
        v = __shfl_sync(0xffffffffu, v, 0);
        if (v >= 32) break;
        int y = ybase + v;

        float4 acc = make_float4(0.f, 0.f, 0.f, 0.f);
        if (y < NYY) {
            int vox = (x * NYY + y) * BV + b;
            int cnt = g_count[vox];
            int off = g_off[vox] + g_bsum[vox >> 10];
            const int* idx = g_idx + off;
            int j = 0;
            for (; j + 1 < cnt; j += 2) {
                int p0 = idx[j];
                int p1 = idx[j + 1];
                float4 a = *(reinterpret_cast<const float4*>(feats + (size_t)p0 * CC) + lane);
                float4 c = *(reinterpret_cast<const float4*>(feats + (size_t)p1 * CC) + lane);
                acc.x += a.x + c.x; acc.y += a.y + c.y;
                acc.z += a.z + c.z; acc.w += a.w + c.w;
            }
            if (j < cnt) {
                float4 a = *(reinterpret_cast<const float4*>(feats + (size_t)idx[j] * CC) + lane);
                acc.x += a.x; acc.y += a.y; acc.z += a.z; acc.w += a.w;
            }
        }
        tile[v][lane*4 + 0] = acc.x;
        tile[v][lane*4 + 1] = acc.y;
        tile[v][lane*4 + 2] = acc.z;
        tile[v][lane*4 + 3] = acc.w;
    }
    __syncthreads();

    // out[b][c][x][y]: warp = 32 consecutive y for one c -> 128B coalesced
    #pragma unroll
    for (int k = 0; k < 8; k++) {
        int i2 = tid + k * 512;
        int c  = i2 >> 5;
        int yy = i2 & 31;
        int y  = ybase + yy;
        if (y < NYY)
            out[((size_t)(b * CC + c) * NXX + x) * NYY + y] = tile[yy][c];
    }
}

// ---------------- launch ----------------
extern "C" void kernel_launch(void* const* d_in, const int* in_sizes, int n_in,
                              void* d_out, int out_size) {
    const float* cam_feats  = (const float*)d_in[0];
    const float* rots       = (const float*)d_in[1];
    const float* trans      = (const float*)d_in[2];
    const float* intrins    = (const float*)d_in[3];
    const float* post_rots  = (const float*)d_in[4];
    const float* post_trans = (const float*)d_in[5];
    float* out = (float*)d_out;

    k_init<<<(NVOX + 255) / 256, 256>>>(rots, trans, intrins, post_rots, post_trans);
    k_geom<<<(NPTS + 255) / 256, 256>>>();
    k_scan1<<<NSCAN_BLOCKS, 256>>>();
    k_scan2<<<1, 256>>>();
    k_fill<<<(NPTS + 255) / 256, 256>>>();

    dim3 ggrid((NYY + 31) / 32, NXX, BV);
    k_gather<<<ggrid, 512>>>(cam_feats, out);
}